// round 4
// baseline (speedup 1.0000x reference)
#include <cuda_runtime.h>
#include <cuda_bf16.h>
#include <cstdint>

#define NNODES 50000
#define NEDGES 800000
#define DF     128

// ---------------------------------------------------------------------------
// Scratch (__device__ globals; no allocations allowed)
// ---------------------------------------------------------------------------
__device__ __align__(16) float g_agg[NNODES * DF];            // fp32 aggregation
__device__ __align__(16) float g_h[NNODES * DF];              // fp32 activations
__device__ __align__(16) __nv_bfloat16 g_xhi[NNODES * DF];    // A operand hi
__device__ __align__(16) __nv_bfloat16 g_xlo[NNODES * DF];    // A operand lo
__device__ __align__(16) __nv_bfloat16 g_aghi[NNODES * DF];   // normalized agg hi
__device__ __align__(16) __nv_bfloat16 g_aglo[NNODES * DF];   // normalized agg lo
__device__ __align__(16) __nv_bfloat16 g_blhi[128 * 128];     // Wl^T hi  [N][K]
__device__ __align__(16) __nv_bfloat16 g_bllo[128 * 128];     // Wl^T lo
__device__ __align__(16) __nv_bfloat16 g_brhi[128 * 128];     // Wr^T hi
__device__ __align__(16) __nv_bfloat16 g_brlo[128 * 128];     // Wr^T lo
__device__ float g_invdeg[NNODES];
__device__ int   g_deg[NNODES];

__device__ __forceinline__ uint32_t smem_u32(const void* p) {
    uint32_t a;
    asm("{ .reg .u64 t; cvta.to.shared.u64 t, %1; cvt.u32.u64 %0, t; }"
        : "=r"(a) : "l"(p));
    return a;
}
__device__ __forceinline__ void ldm4(uint32_t* r, uint32_t addr) {
    asm volatile("ldmatrix.sync.aligned.m8n8.x4.shared.b16 {%0,%1,%2,%3}, [%4];"
                 : "=r"(r[0]), "=r"(r[1]), "=r"(r[2]), "=r"(r[3]) : "r"(addr));
}
__device__ __forceinline__ void mma16816(float* c, const uint32_t* a,
                                         uint32_t b0, uint32_t b1) {
    asm volatile(
        "mma.sync.aligned.m16n8k16.row.col.f32.bf16.bf16.f32 "
        "{%0,%1,%2,%3}, {%4,%5,%6,%7}, {%8,%9}, {%0,%1,%2,%3};"
        : "+f"(c[0]), "+f"(c[1]), "+f"(c[2]), "+f"(c[3])
        : "r"(a[0]), "r"(a[1]), "r"(a[2]), "r"(a[3]), "r"(b0), "r"(b1));
}

// ---------------------------------------------------------------------------
// Utility kernels
// ---------------------------------------------------------------------------
__global__ void k_zero_deg() {
    int i = blockIdx.x * blockDim.x + threadIdx.x;
    if (i < NNODES) g_deg[i] = 0;
}
__global__ void k_count_deg(const int* __restrict__ ei) {
    int e = blockIdx.x * blockDim.x + threadIdx.x;
    if (e < NEDGES) atomicAdd(&g_deg[ei[NEDGES + e]], 1);
}
__global__ void k_invdeg() {
    int i = blockIdx.x * blockDim.x + threadIdx.x;
    if (i < NNODES) g_invdeg[i] = 1.0f / fmaxf((float)g_deg[i], 1.0f);
}
__global__ void k_zero_agg() {
    int i = blockIdx.x * blockDim.x + threadIdx.x;
    if (i < (NNODES * DF) / 4)
        ((float4*)g_agg)[i] = make_float4(0.f, 0.f, 0.f, 0.f);
}

// Edge scatter: one warp per edge, vec4 global reduction.
__global__ void k_scatter(const float* __restrict__ in, const int* __restrict__ ei) {
    int t = blockIdx.x * blockDim.x + threadIdx.x;
    int e = t >> 5, lane = t & 31;
    if (e >= NEDGES) return;
    int src = ei[e];
    int dst = ei[NEDGES + e];
    float4 v = *(const float4*)(in + (size_t)src * DF + lane * 4);
    float* p = g_agg + (size_t)dst * DF + lane * 4;
    asm volatile("red.global.add.v4.f32 [%0], {%1, %2, %3, %4};"
                 :: "l"(p), "f"(v.x), "f"(v.y), "f"(v.z), "f"(v.w) : "memory");
}

// fp32 -> bf16 hi/lo split (optionally scaled by invdeg) for the GEMM A operand.
__global__ void k_split(const float4* __restrict__ in,
                        __nv_bfloat162* __restrict__ hi,
                        __nv_bfloat162* __restrict__ lo,
                        const float* __restrict__ invdeg) {
    int i = blockIdx.x * blockDim.x + threadIdx.x;
    if (i >= (NNODES * DF) / 4) return;
    float4 v = in[i];
    if (invdeg) {
        float s = invdeg[i >> 5];
        v.x *= s; v.y *= s; v.z *= s; v.w *= s;
    }
    __nv_bfloat16 hx = __float2bfloat16(v.x), hy = __float2bfloat16(v.y);
    __nv_bfloat16 hz = __float2bfloat16(v.z), hw = __float2bfloat16(v.w);
    hi[i * 2 + 0] = __halves2bfloat162(hx, hy);
    hi[i * 2 + 1] = __halves2bfloat162(hz, hw);
    lo[i * 2 + 0] = __halves2bfloat162(
        __float2bfloat16(v.x - __bfloat162float(hx)),
        __float2bfloat16(v.y - __bfloat162float(hy)));
    lo[i * 2 + 1] = __halves2bfloat162(
        __float2bfloat16(v.z - __bfloat162float(hz)),
        __float2bfloat16(v.w - __bfloat162float(hw)));
}

// W [K=128][N] fp32 row-major -> Wt hi/lo [N][K=128] bf16 (mma B operand)
__global__ void k_w_prep(const float* __restrict__ W,
                         __nv_bfloat16* __restrict__ hi,
                         __nv_bfloat16* __restrict__ lo, int N) {
    int i = blockIdx.x * blockDim.x + threadIdx.x;
    if (i >= N * 128) return;
    int n = i >> 7, k = i & 127;
    float w = W[k * N + n];
    __nv_bfloat16 h = __float2bfloat16(w);
    hi[i] = h;
    lo[i] = __float2bfloat16(w - __bfloat162float(h));
}

// ---------------------------------------------------------------------------
// mma.sync fused GEMM:
//  D = Xhi@Wl_hi + Xlo@Wl_hi + Xhi@Wl_lo + Ahi@Wr_hi + Alo@Wr_hi + Ahi@Wr_lo
//  (12 K=64 segments), epilogue: +bias, optional relu, fp32 out (+ fused split)
//  CTA: 128 x TN tile, 256 threads = 8 warps (2m x 4n), warp tile 64 x TN/4.
// ---------------------------------------------------------------------------
#define ROWP 72   // padded SMEM row stride in bf16 elements (ldmatrix conflict-free)

template<int TN, bool RELU, bool SPLIT>
__global__ void __launch_bounds__(256, 2)
k_gemm_mma(const __nv_bfloat16* __restrict__ xhi, const __nv_bfloat16* __restrict__ xlo,
           const __nv_bfloat16* __restrict__ aghi, const __nv_bfloat16* __restrict__ aglo,
           const __nv_bfloat16* __restrict__ blhi, const __nv_bfloat16* __restrict__ bllo,
           const __nv_bfloat16* __restrict__ brhi, const __nv_bfloat16* __restrict__ brlo,
           const float* __restrict__ bias,
           float* __restrict__ outF,
           __nv_bfloat16* __restrict__ ohi, __nv_bfloat16* __restrict__ olo) {
    extern __shared__ __align__(16) char smem[];   // A: 128*ROWP bf16, B: TN*ROWP bf16
    constexpr int NTC = TN / 4;      // cols per warp (32 / 16)
    constexpr int NP  = NTC / 16;    // ldmatrix n16 pairs per warp (2 / 1)
    constexpr int NT  = NTC / 8;     // n8 tiles per warp (4 / 2)

    const int tid = threadIdx.x;
    const int lane = tid & 31, wid = tid >> 5;
    const int warp_m = wid >> 2, warp_n = wid & 3;
    const int m0 = blockIdx.x * 128;

    const uint32_t aBase = smem_u32(smem);
    const uint32_t bBase = aBase + 128 * ROWP * 2;

    // ldmatrix per-lane element offsets
    const int aLaneOff = (warp_m * 64 + (lane & 15)) * ROWP + (lane >> 4) * 8;
    const int bLaneOff = (warp_n * NTC + (lane & 7) + ((lane >> 4) & 1) * 8) * ROWP
                       + ((lane >> 3) & 1) * 8;

    float acc[4][NT][4];
#pragma unroll
    for (int mt = 0; mt < 4; ++mt)
#pragma unroll
        for (int nt = 0; nt < NT; ++nt)
#pragma unroll
            for (int r = 0; r < 4; ++r) acc[mt][nt][r] = 0.f;

    const __nv_bfloat16* aPtr[4] = {xhi, xlo, aghi, aglo};
    const __nv_bfloat16* bPtr[4] = {blhi, bllo, brhi, brlo};
    const int  aSel[12] = {0, 1, 0, 0, 1, 0, 2, 3, 2, 2, 3, 2};
    const int  bSel[12] = {0, 0, 1, 0, 0, 1, 2, 2, 3, 2, 2, 3};
    const int  kOff[12] = {0, 0, 0, 64, 64, 64, 0, 0, 0, 64, 64, 64};

    for (int s = 0; s < 12; ++s) {
        const __nv_bfloat16* ap = aPtr[aSel[s]] + kOff[s];
        const __nv_bfloat16* bp = bPtr[bSel[s]] + kOff[s];

        // A tile: 128 rows x 64 bf16 -> SMEM (row stride ROWP)
#pragma unroll
        for (int i = 0; i < 4; ++i) {
            int idx = tid + i * 256;          // 0..1023
            int row = idx >> 3, q = idx & 7;  // q: 16B chunk (8 bf16)
            uint4 v = make_uint4(0, 0, 0, 0);
            int grow = m0 + row;
            if (grow < NNODES)
                v = *(const uint4*)(ap + (size_t)grow * DF + q * 8);
            *(uint4*)(smem + (row * ROWP + q * 8) * 2) = v;
        }
        // B tile: TN rows x 64 bf16
#pragma unroll
        for (int i = 0; i < TN / 32; ++i) {
            int idx = tid + i * 256;
            int row = idx >> 3, q = idx & 7;
            uint4 v = *(const uint4*)(bp + (size_t)row * DF + q * 8);
            *(uint4*)(smem + 128 * ROWP * 2 + (row * ROWP + q * 8) * 2) = v;
        }
        __syncthreads();

#pragma unroll
        for (int kk = 0; kk < 4; ++kk) {
            uint32_t a[4][4];
#pragma unroll
            for (int mt = 0; mt < 4; ++mt)
                ldm4(a[mt], aBase + 2u * (aLaneOff + mt * 16 * ROWP + kk * 16));
            uint32_t b[NP][4];
#pragma unroll
            for (int np = 0; np < NP; ++np)
                ldm4(b[np], bBase + 2u * (bLaneOff + np * 16 * ROWP + kk * 16));
#pragma unroll
            for (int mt = 0; mt < 4; ++mt)
#pragma unroll
                for (int np = 0; np < NP; ++np) {
                    mma16816(acc[mt][np * 2 + 0], a[mt], b[np][0], b[np][1]);
                    mma16816(acc[mt][np * 2 + 1], a[mt], b[np][2], b[np][3]);
                }
        }
        __syncthreads();
    }

    // Epilogue: thread holds rows (base, base+8), col pair (c, c+1) per n-tile.
#pragma unroll
    for (int mt = 0; mt < 4; ++mt) {
        int row0 = m0 + warp_m * 64 + mt * 16 + (lane >> 2);
#pragma unroll
        for (int nt = 0; nt < NT; ++nt) {
            int col = warp_n * NTC + nt * 8 + (lane & 3) * 2;
            float bx = bias[col], by = bias[col + 1];
#pragma unroll
            for (int half = 0; half < 2; ++half) {
                int row = row0 + half * 8;
                if (row >= NNODES) continue;
                float v0 = acc[mt][nt][half * 2 + 0] + bx;
                float v1 = acc[mt][nt][half * 2 + 1] + by;
                if (RELU) { v0 = fmaxf(v0, 0.f); v1 = fmaxf(v1, 0.f); }
                *(float2*)(outF + (size_t)row * TN + col) = make_float2(v0, v1);
                if (SPLIT) {
                    __nv_bfloat16 h0 = __float2bfloat16(v0);
                    __nv_bfloat16 h1 = __float2bfloat16(v1);
                    *(__nv_bfloat162*)(ohi + (size_t)row * TN + col) =
                        __halves2bfloat162(h0, h1);
                    *(__nv_bfloat162*)(olo + (size_t)row * TN + col) =
                        __halves2bfloat162(
                            __float2bfloat16(v0 - __bfloat162float(h0)),
                            __float2bfloat16(v1 - __bfloat162float(h1)));
                }
            }
        }
    }
}

// ---------------------------------------------------------------------------
// Launch
// ---------------------------------------------------------------------------
extern "C" void kernel_launch(void* const* d_in, const int* in_sizes, int n_in,
                              void* d_out, int out_size) {
    const float* x   = (const float*)d_in[0];
    const int*   ei  = (const int*)d_in[1];
    const float* Wl1 = (const float*)d_in[2];
    const float* Wr1 = (const float*)d_in[3];
    const float* b1  = (const float*)d_in[4];
    const float* Wl2 = (const float*)d_in[5];
    const float* Wr2 = (const float*)d_in[6];
    const float* b2  = (const float*)d_in[7];
    const float* Wl3 = (const float*)d_in[8];
    const float* Wr3 = (const float*)d_in[9];
    const float* b3  = (const float*)d_in[10];
    float* out = (float*)d_out;

    float *h = nullptr, *agg = nullptr, *invdeg = nullptr;
    __nv_bfloat16 *xhi, *xlo, *aghi, *aglo, *blhi, *bllo, *brhi, *brlo;
    cudaGetSymbolAddress((void**)&h, g_h);
    cudaGetSymbolAddress((void**)&agg, g_agg);
    cudaGetSymbolAddress((void**)&invdeg, g_invdeg);
    cudaGetSymbolAddress((void**)&xhi, g_xhi);
    cudaGetSymbolAddress((void**)&xlo, g_xlo);
    cudaGetSymbolAddress((void**)&aghi, g_aghi);
    cudaGetSymbolAddress((void**)&aglo, g_aglo);
    cudaGetSymbolAddress((void**)&blhi, g_blhi);
    cudaGetSymbolAddress((void**)&bllo, g_bllo);
    cudaGetSymbolAddress((void**)&brhi, g_brhi);
    cudaGetSymbolAddress((void**)&brlo, g_brlo);

    const int ZB = 256;
    const int nodeBlocks  = (NNODES + ZB - 1) / ZB;
    const int edgeBlocks  = (NEDGES + ZB - 1) / ZB;
    const int aggBlocks   = ((NNODES * DF) / 4 + ZB - 1) / ZB;
    const int scatBlocks  = (NEDGES * 32) / ZB;
    const int gemmBlocks  = (NNODES + 127) / 128;          // 391
    const int wBlocks128  = (128 * 128 + ZB - 1) / ZB;
    const int wBlocks64   = (128 * 64 + ZB - 1) / ZB;
    const int smem128 = (128 + 128) * ROWP * 2;            // 36864
    const int smem64  = (128 + 64) * ROWP * 2;             // 27648

    // Degree + invdeg
    k_zero_deg<<<nodeBlocks, ZB>>>();
    k_count_deg<<<edgeBlocks, ZB>>>(ei);
    k_invdeg<<<nodeBlocks, ZB>>>();

    // A operand for layer 1
    k_split<<<aggBlocks, ZB>>>((const float4*)x, (__nv_bfloat162*)xhi,
                               (__nv_bfloat162*)xlo, nullptr);

    // ---- Layer 1 ----
    k_zero_agg<<<aggBlocks, ZB>>>();
    k_scatter<<<scatBlocks, ZB>>>(x, ei);
    k_split<<<aggBlocks, ZB>>>((const float4*)agg, (__nv_bfloat162*)aghi,
                               (__nv_bfloat162*)aglo, invdeg);
    k_w_prep<<<wBlocks128, ZB>>>(Wl1, blhi, bllo, 128);
    k_w_prep<<<wBlocks128, ZB>>>(Wr1, brhi, brlo, 128);
    k_gemm_mma<128, true, true><<<gemmBlocks, 256, smem128>>>(
        xhi, xlo, aghi, aglo, blhi, bllo, brhi, brlo, b1, h, xhi, xlo);

    // ---- Layer 2 ----
    k_zero_agg<<<aggBlocks, ZB>>>();
    k_scatter<<<scatBlocks, ZB>>>(h, ei);
    k_split<<<aggBlocks, ZB>>>((const float4*)agg, (__nv_bfloat162*)aghi,
                               (__nv_bfloat162*)aglo, invdeg);
    k_w_prep<<<wBlocks128, ZB>>>(Wl2, blhi, bllo, 128);
    k_w_prep<<<wBlocks128, ZB>>>(Wr2, brhi, brlo, 128);
    k_gemm_mma<128, true, true><<<gemmBlocks, 256, smem128>>>(
        xhi, xlo, aghi, aglo, blhi, bllo, brhi, brlo, b2, h, xhi, xlo);

    // ---- Layer 3 (N=64, no relu, no split) ----
    k_zero_agg<<<aggBlocks, ZB>>>();
    k_scatter<<<scatBlocks, ZB>>>(h, ei);
    k_split<<<aggBlocks, ZB>>>((const float4*)agg, (__nv_bfloat162*)aghi,
                               (__nv_bfloat162*)aglo, invdeg);
    k_w_prep<<<wBlocks64, ZB>>>(Wl3, blhi, bllo, 64);
    k_w_prep<<<wBlocks64, ZB>>>(Wr3, brhi, brlo, 64);
    k_gemm_mma<64, false, false><<<gemmBlocks, 256, smem64>>>(
        xhi, xlo, aghi, aglo, blhi, bllo, brhi, brlo, b3, out, nullptr, nullptr);
}

// round 5
// speedup vs baseline: 1.3498x; 1.3498x over previous
#include <cuda_runtime.h>
#include <cuda_bf16.h>
#include <cstdint>

#define NNODES 50000
#define NEDGES 800000
#define DF     128

// ---------------------------------------------------------------------------
// Scratch (__device__ globals; no allocations allowed)
// ---------------------------------------------------------------------------
__device__ __align__(16) float g_h[NNODES * DF];              // fp32 activations
__device__ __align__(16) __nv_bfloat16 g_xhi[NNODES * DF];    // self operand hi
__device__ __align__(16) __nv_bfloat16 g_xlo[NNODES * DF];    // self operand lo
__device__ __align__(16) __nv_bfloat16 g_aghi[NNODES * DF];   // normalized agg hi
__device__ __align__(16) __nv_bfloat16 g_aglo[NNODES * DF];   // normalized agg lo
__device__ __align__(16) __nv_bfloat16 g_whi[81920];          // all W^T hi (6 mats)
__device__ __align__(16) __nv_bfloat16 g_wlo[81920];          // all W^T lo
__device__ float g_invdeg[NNODES];
__device__ int   g_deg[NNODES];
__device__ int   g_rowstart[NNODES];
__device__ int   g_cursor[NNODES];
__device__ int   g_csrc[NEDGES];

// Weight buffer offsets (bf16 elements)
#define W_L1L 0
#define W_L1R 16384
#define W_L2L 32768
#define W_L2R 49152
#define W_L3L 65536
#define W_L3R 73728

__device__ __forceinline__ uint32_t smem_u32(const void* p) {
    uint32_t a;
    asm("{ .reg .u64 t; cvta.to.shared.u64 t, %1; cvt.u32.u64 %0, t; }"
        : "=r"(a) : "l"(p));
    return a;
}
__device__ __forceinline__ void ldm4(uint32_t* r, uint32_t addr) {
    asm volatile("ldmatrix.sync.aligned.m8n8.x4.shared.b16 {%0,%1,%2,%3}, [%4];"
                 : "=r"(r[0]), "=r"(r[1]), "=r"(r[2]), "=r"(r[3]) : "r"(addr));
}
__device__ __forceinline__ void mma16816(float* c, const uint32_t* a,
                                         uint32_t b0, uint32_t b1) {
    asm volatile(
        "mma.sync.aligned.m16n8k16.row.col.f32.bf16.bf16.f32 "
        "{%0,%1,%2,%3}, {%4,%5,%6,%7}, {%8,%9}, {%0,%1,%2,%3};"
        : "+f"(c[0]), "+f"(c[1]), "+f"(c[2]), "+f"(c[3])
        : "r"(a[0]), "r"(a[1]), "r"(a[2]), "r"(a[3]), "r"(b0), "r"(b1));
}

// ---------------------------------------------------------------------------
// CSR build
// ---------------------------------------------------------------------------
__global__ void k_zero_deg() {
    int i = blockIdx.x * blockDim.x + threadIdx.x;
    if (i < NNODES) g_deg[i] = 0;
}
__global__ void k_count_deg(const int* __restrict__ ei) {
    int e = blockIdx.x * blockDim.x + threadIdx.x;
    if (e < NEDGES) atomicAdd(&g_deg[ei[NEDGES + e]], 1);
}

// Single-CTA exclusive scan of deg -> rowstart (+cursor copy, +invdeg).
__global__ void __launch_bounds__(1024) k_scan() {
    __shared__ int warp_sums[32];
    __shared__ int s_carry;
    const int tid = threadIdx.x, lane = tid & 31, w = tid >> 5;
    if (tid == 0) s_carry = 0;
    __syncthreads();
    for (int base = 0; base < NNODES; base += 1024) {
        int i = base + tid;
        int d = (i < NNODES) ? g_deg[i] : 0;
        int v = d;
#pragma unroll
        for (int o = 1; o < 32; o <<= 1) {
            int t = __shfl_up_sync(~0u, v, o);
            if (lane >= o) v += t;
        }
        if (lane == 31) warp_sums[w] = v;
        __syncthreads();
        if (w == 0) {
            int s = warp_sums[lane];
#pragma unroll
            for (int o = 1; o < 32; o <<= 1) {
                int t = __shfl_up_sync(~0u, s, o);
                if (lane >= o) s += t;
            }
            warp_sums[lane] = s;
        }
        __syncthreads();
        int excl = v - d + (w > 0 ? warp_sums[w - 1] : 0) + s_carry;
        if (i < NNODES) {
            g_rowstart[i] = excl;
            g_cursor[i]   = excl;
            g_invdeg[i]   = 1.0f / fmaxf((float)d, 1.0f);
        }
        __syncthreads();
        if (tid == 1023) s_carry = excl + d;
        __syncthreads();
    }
}

__global__ void k_fill_csr(const int* __restrict__ ei) {
    int e = blockIdx.x * blockDim.x + threadIdx.x;
    if (e >= NEDGES) return;
    int src = ei[e];
    int dst = ei[NEDGES + e];
    int slot = atomicAdd(&g_cursor[dst], 1);
    g_csrc[slot] = src;
}

// ---------------------------------------------------------------------------
// Gather-aggregate: one warp per node. acc = sum_{j in N(i)} in[j]; then
// normalize by invdeg and write bf16 hi/lo GEMM operand directly.
// ---------------------------------------------------------------------------
__global__ void __launch_bounds__(256) k_gather(const float* __restrict__ in) {
    int node = (blockIdx.x * blockDim.x + threadIdx.x) >> 5;
    int lane = threadIdx.x & 31;
    if (node >= NNODES) return;
    int start = g_rowstart[node];
    int deg = g_deg[node];
    const int* lst = g_csrc + start;

    float4 a0 = make_float4(0.f, 0.f, 0.f, 0.f);
    float4 a1 = make_float4(0.f, 0.f, 0.f, 0.f);
    int j = 0;
    for (; j + 2 <= deg; j += 2) {
        int s0 = lst[j], s1 = lst[j + 1];
        float4 v0 = *(const float4*)(in + (size_t)s0 * DF + lane * 4);
        float4 v1 = *(const float4*)(in + (size_t)s1 * DF + lane * 4);
        a0.x += v0.x; a0.y += v0.y; a0.z += v0.z; a0.w += v0.w;
        a1.x += v1.x; a1.y += v1.y; a1.z += v1.z; a1.w += v1.w;
    }
    if (j < deg) {
        int s0 = lst[j];
        float4 v0 = *(const float4*)(in + (size_t)s0 * DF + lane * 4);
        a0.x += v0.x; a0.y += v0.y; a0.z += v0.z; a0.w += v0.w;
    }
    float s = g_invdeg[node];
    float4 v;
    v.x = (a0.x + a1.x) * s; v.y = (a0.y + a1.y) * s;
    v.z = (a0.z + a1.z) * s; v.w = (a0.w + a1.w) * s;

    __nv_bfloat16 hx = __float2bfloat16(v.x), hy = __float2bfloat16(v.y);
    __nv_bfloat16 hz = __float2bfloat16(v.z), hw = __float2bfloat16(v.w);
    size_t o = (size_t)node * DF + lane * 4;
    *(__nv_bfloat162*)(g_aghi + o)     = __halves2bfloat162(hx, hy);
    *(__nv_bfloat162*)(g_aghi + o + 2) = __halves2bfloat162(hz, hw);
    *(__nv_bfloat162*)(g_aglo + o) = __halves2bfloat162(
        __float2bfloat16(v.x - __bfloat162float(hx)),
        __float2bfloat16(v.y - __bfloat162float(hy)));
    *(__nv_bfloat162*)(g_aglo + o + 2) = __halves2bfloat162(
        __float2bfloat16(v.z - __bfloat162float(hz)),
        __float2bfloat16(v.w - __bfloat162float(hw)));
}

// fp32 -> bf16 hi/lo split for the layer-1 self operand.
__global__ void k_split_x(const float4* __restrict__ in) {
    int i = blockIdx.x * blockDim.x + threadIdx.x;
    if (i >= (NNODES * DF) / 4) return;
    float4 v = in[i];
    __nv_bfloat16 hx = __float2bfloat16(v.x), hy = __float2bfloat16(v.y);
    __nv_bfloat16 hz = __float2bfloat16(v.z), hw = __float2bfloat16(v.w);
    __nv_bfloat162* hi = (__nv_bfloat162*)g_xhi;
    __nv_bfloat162* lo = (__nv_bfloat162*)g_xlo;
    hi[i * 2 + 0] = __halves2bfloat162(hx, hy);
    hi[i * 2 + 1] = __halves2bfloat162(hz, hw);
    lo[i * 2 + 0] = __halves2bfloat162(
        __float2bfloat16(v.x - __bfloat162float(hx)),
        __float2bfloat16(v.y - __bfloat162float(hy)));
    lo[i * 2 + 1] = __halves2bfloat162(
        __float2bfloat16(v.z - __bfloat162float(hz)),
        __float2bfloat16(v.w - __bfloat162float(hw)));
}

// All six W [K=128][N] fp32 -> Wt hi/lo [N][K=128] bf16, one kernel.
__global__ void k_w_prep_all(const float* __restrict__ Wl1, const float* __restrict__ Wr1,
                             const float* __restrict__ Wl2, const float* __restrict__ Wr2,
                             const float* __restrict__ Wl3, const float* __restrict__ Wr3) {
    int i = blockIdx.x * blockDim.x + threadIdx.x;
    if (i >= 81920) return;
    const float* W;
    int N, li;
    if (i < 32768) { N = 128; if (i < 16384) { W = Wl1; li = i; } else { W = Wr1; li = i - 16384; } }
    else if (i < 65536) { N = 128; if (i < 49152) { W = Wl2; li = i - 32768; } else { W = Wr2; li = i - 49152; } }
    else { N = 64; if (i < 73728) { W = Wl3; li = i - 65536; } else { W = Wr3; li = i - 73728; } }
    int n = li >> 7, k = li & 127;
    float w = W[k * N + n];
    __nv_bfloat16 h = __float2bfloat16(w);
    g_whi[i] = h;
    g_wlo[i] = __float2bfloat16(w - __bfloat162float(h));
}

// ---------------------------------------------------------------------------
// mma.sync fused GEMM (unchanged from R4):
//  D = Xhi@Wl_hi + Xlo@Wl_hi + Xhi@Wl_lo + Ahi@Wr_hi + Alo@Wr_hi + Ahi@Wr_lo
//  CTA: 128 x TN tile, 256 threads = 8 warps (2m x 4n), warp tile 64 x TN/4.
// ---------------------------------------------------------------------------
#define ROWP 72   // padded SMEM row stride in bf16 elements

template<int TN, bool RELU, bool SPLIT>
__global__ void __launch_bounds__(256, 2)
k_gemm_mma(const __nv_bfloat16* __restrict__ blhi, const __nv_bfloat16* __restrict__ bllo,
           const __nv_bfloat16* __restrict__ brhi, const __nv_bfloat16* __restrict__ brlo,
           const float* __restrict__ bias,
           float* __restrict__ outF,
           __nv_bfloat16* __restrict__ ohi, __nv_bfloat16* __restrict__ olo) {
    extern __shared__ __align__(16) char smem[];
    constexpr int NTC = TN / 4;
    constexpr int NP  = NTC / 16;
    constexpr int NT  = NTC / 8;

    const int tid = threadIdx.x;
    const int lane = tid & 31, wid = tid >> 5;
    const int warp_m = wid >> 2, warp_n = wid & 3;
    const int m0 = blockIdx.x * 128;

    const uint32_t aBase = smem_u32(smem);
    const uint32_t bBase = aBase + 128 * ROWP * 2;

    const int aLaneOff = (warp_m * 64 + (lane & 15)) * ROWP + (lane >> 4) * 8;
    const int bLaneOff = (warp_n * NTC + (lane & 7) + ((lane >> 4) & 1) * 8) * ROWP
                       + ((lane >> 3) & 1) * 8;

    float acc[4][NT][4];
#pragma unroll
    for (int mt = 0; mt < 4; ++mt)
#pragma unroll
        for (int nt = 0; nt < NT; ++nt)
#pragma unroll
            for (int r = 0; r < 4; ++r) acc[mt][nt][r] = 0.f;

    const __nv_bfloat16* aPtr[4] = {g_xhi, g_xlo, g_aghi, g_aglo};
    const __nv_bfloat16* bPtr[4] = {blhi, bllo, brhi, brlo};
    const int  aSel[12] = {0, 1, 0, 0, 1, 0, 2, 3, 2, 2, 3, 2};
    const int  bSel[12] = {0, 0, 1, 0, 0, 1, 2, 2, 3, 2, 2, 3};
    const int  kOff[12] = {0, 0, 0, 64, 64, 64, 0, 0, 0, 64, 64, 64};

    for (int s = 0; s < 12; ++s) {
        const __nv_bfloat16* ap = aPtr[aSel[s]] + kOff[s];
        const __nv_bfloat16* bp = bPtr[bSel[s]] + kOff[s];

#pragma unroll
        for (int i = 0; i < 4; ++i) {
            int idx = tid + i * 256;
            int row = idx >> 3, q = idx & 7;
            uint4 v = make_uint4(0, 0, 0, 0);
            int grow = m0 + row;
            if (grow < NNODES)
                v = *(const uint4*)(ap + (size_t)grow * DF + q * 8);
            *(uint4*)(smem + (row * ROWP + q * 8) * 2) = v;
        }
#pragma unroll
        for (int i = 0; i < TN / 32; ++i) {
            int idx = tid + i * 256;
            int row = idx >> 3, q = idx & 7;
            uint4 v = *(const uint4*)(bp + (size_t)row * DF + q * 8);
            *(uint4*)(smem + 128 * ROWP * 2 + (row * ROWP + q * 8) * 2) = v;
        }
        __syncthreads();

#pragma unroll
        for (int kk = 0; kk < 4; ++kk) {
            uint32_t a[4][4];
#pragma unroll
            for (int mt = 0; mt < 4; ++mt)
                ldm4(a[mt], aBase + 2u * (aLaneOff + mt * 16 * ROWP + kk * 16));
            uint32_t b[NP][4];
#pragma unroll
            for (int np = 0; np < NP; ++np)
                ldm4(b[np], bBase + 2u * (bLaneOff + np * 16 * ROWP + kk * 16));
#pragma unroll
            for (int mt = 0; mt < 4; ++mt)
#pragma unroll
                for (int np = 0; np < NP; ++np) {
                    mma16816(acc[mt][np * 2 + 0], a[mt], b[np][0], b[np][1]);
                    mma16816(acc[mt][np * 2 + 1], a[mt], b[np][2], b[np][3]);
                }
        }
        __syncthreads();
    }

#pragma unroll
    for (int mt = 0; mt < 4; ++mt) {
        int row0 = m0 + warp_m * 64 + mt * 16 + (lane >> 2);
#pragma unroll
        for (int nt = 0; nt < NT; ++nt) {
            int col = warp_n * NTC + nt * 8 + (lane & 3) * 2;
            float bx = bias[col], by = bias[col + 1];
#pragma unroll
            for (int half = 0; half < 2; ++half) {
                int row = row0 + half * 8;
                if (row >= NNODES) continue;
                float v0 = acc[mt][nt][half * 2 + 0] + bx;
                float v1 = acc[mt][nt][half * 2 + 1] + by;
                if (RELU) { v0 = fmaxf(v0, 0.f); v1 = fmaxf(v1, 0.f); }
                *(float2*)(outF + (size_t)row * TN + col) = make_float2(v0, v1);
                if (SPLIT) {
                    __nv_bfloat16 h0 = __float2bfloat16(v0);
                    __nv_bfloat16 h1 = __float2bfloat16(v1);
                    *(__nv_bfloat162*)(ohi + (size_t)row * TN + col) =
                        __halves2bfloat162(h0, h1);
                    *(__nv_bfloat162*)(olo + (size_t)row * TN + col) =
                        __halves2bfloat162(
                            __float2bfloat16(v0 - __bfloat162float(h0)),
                            __float2bfloat16(v1 - __bfloat162float(h1)));
                }
            }
        }
    }
}

// ---------------------------------------------------------------------------
// Launch
// ---------------------------------------------------------------------------
extern "C" void kernel_launch(void* const* d_in, const int* in_sizes, int n_in,
                              void* d_out, int out_size) {
    const float* x   = (const float*)d_in[0];
    const int*   ei  = (const int*)d_in[1];
    const float* Wl1 = (const float*)d_in[2];
    const float* Wr1 = (const float*)d_in[3];
    const float* b1  = (const float*)d_in[4];
    const float* Wl2 = (const float*)d_in[5];
    const float* Wr2 = (const float*)d_in[6];
    const float* b2  = (const float*)d_in[7];
    const float* Wl3 = (const float*)d_in[8];
    const float* Wr3 = (const float*)d_in[9];
    const float* b3  = (const float*)d_in[10];
    float* out = (float*)d_out;

    float *h = nullptr;
    __nv_bfloat16 *xhi, *xlo, *whi, *wlo;
    cudaGetSymbolAddress((void**)&h, g_h);
    cudaGetSymbolAddress((void**)&xhi, g_xhi);
    cudaGetSymbolAddress((void**)&xlo, g_xlo);
    cudaGetSymbolAddress((void**)&whi, g_whi);
    cudaGetSymbolAddress((void**)&wlo, g_wlo);

    const int ZB = 256;
    const int nodeBlocks = (NNODES + ZB - 1) / ZB;
    const int edgeBlocks = (NEDGES + ZB - 1) / ZB;
    const int featBlocks = ((NNODES * DF) / 4 + ZB - 1) / ZB;
    const int gathBlocks = (NNODES * 32 + ZB - 1) / ZB;     // 6250
    const int gemmBlocks = (NNODES + 127) / 128;            // 391
    const int wBlocks    = (81920 + ZB - 1) / ZB;
    const int smem128 = (128 + 128) * ROWP * 2;             // 36864
    const int smem64  = (128 + 64) * ROWP * 2;              // 27648

    // CSR build (once per launch)
    k_zero_deg<<<nodeBlocks, ZB>>>();
    k_count_deg<<<edgeBlocks, ZB>>>(ei);
    k_scan<<<1, 1024>>>();
    k_fill_csr<<<edgeBlocks, ZB>>>(ei);

    // Operand prep
    k_w_prep_all<<<wBlocks, ZB>>>(Wl1, Wr1, Wl2, Wr2, Wl3, Wr3);
    k_split_x<<<featBlocks, ZB>>>((const float4*)x);

    // ---- Layer 1 ----
    k_gather<<<gathBlocks, ZB>>>(x);
    k_gemm_mma<128, true, true><<<gemmBlocks, 256, smem128>>>(
        whi + W_L1L, wlo + W_L1L, whi + W_L1R, wlo + W_L1R, b1, h, xhi, xlo);

    // ---- Layer 2 ----
    k_gather<<<gathBlocks, ZB>>>(h);
    k_gemm_mma<128, true, true><<<gemmBlocks, 256, smem128>>>(
        whi + W_L2L, wlo + W_L2L, whi + W_L2R, wlo + W_L2R, b2, h, xhi, xlo);

    // ---- Layer 3 (N=64, no relu, no split) ----
    k_gather<<<gathBlocks, ZB>>>(h);
    k_gemm_mma<64, false, false><<<gemmBlocks, 256, smem64>>>(
        whi + W_L3L, wlo + W_L3L, whi + W_L3R, wlo + W_L3R, b3, out, nullptr, nullptr);
}

// round 6
// speedup vs baseline: 1.7086x; 1.2658x over previous
#include <cuda_runtime.h>
#include <cuda_fp16.h>
#include <cstdint>

#define NNODES 50000
#define NEDGES 800000
#define DF     128

// ---------------------------------------------------------------------------
// Scratch (__device__ globals; no allocations allowed)
// ---------------------------------------------------------------------------
__device__ __align__(16) __half g_xhi[NNODES * DF];   // self operand hi (also layer output)
__device__ __align__(16) __half g_xlo[NNODES * DF];   // self operand lo
__device__ __align__(16) __half g_aghi[NNODES * DF];  // normalized agg hi
__device__ __align__(16) __half g_aglo[NNODES * DF];  // normalized agg lo
__device__ __align__(16) __half g_w[81920];           // all W^T fp16 (6 mats)
__device__ float g_invdeg[NNODES];
__device__ int   g_deg[NNODES];
__device__ int   g_rowstart[NNODES];
__device__ int   g_cursor[NNODES];
__device__ int   g_csrc[NEDGES];

// Weight buffer offsets (fp16 elements), layout [N][K=128]
#define W_L1L 0
#define W_L1R 16384
#define W_L2L 32768
#define W_L2R 49152
#define W_L3L 65536
#define W_L3R 73728

__device__ __forceinline__ uint32_t smem_u32(const void* p) {
    uint32_t a;
    asm("{ .reg .u64 t; cvta.to.shared.u64 t, %1; cvt.u32.u64 %0, t; }"
        : "=r"(a) : "l"(p));
    return a;
}
__device__ __forceinline__ void ldm4(uint32_t* r, uint32_t addr) {
    asm volatile("ldmatrix.sync.aligned.m8n8.x4.shared.b16 {%0,%1,%2,%3}, [%4];"
                 : "=r"(r[0]), "=r"(r[1]), "=r"(r[2]), "=r"(r[3]) : "r"(addr));
}
__device__ __forceinline__ void mma16816(float* c, const uint32_t* a,
                                         uint32_t b0, uint32_t b1) {
    asm volatile(
        "mma.sync.aligned.m16n8k16.row.col.f32.f16.f16.f32 "
        "{%0,%1,%2,%3}, {%4,%5,%6,%7}, {%8,%9}, {%0,%1,%2,%3};"
        : "+f"(c[0]), "+f"(c[1]), "+f"(c[2]), "+f"(c[3])
        : "r"(a[0]), "r"(a[1]), "r"(a[2]), "r"(a[3]), "r"(b0), "r"(b1));
}
__device__ __forceinline__ void cpa16(uint32_t dst, const void* src) {
    asm volatile("cp.async.cg.shared.global [%0], [%1], 16;" :: "r"(dst), "l"(src));
}
#define CPA_COMMIT() asm volatile("cp.async.commit_group;" ::: "memory")
#define CPA_WAIT(n)  asm volatile("cp.async.wait_group %0;" :: "n"(n) : "memory")

// ---------------------------------------------------------------------------
// CSR build
// ---------------------------------------------------------------------------
__global__ void k_zero_deg() {
    int i = blockIdx.x * blockDim.x + threadIdx.x;
    if (i < NNODES) g_deg[i] = 0;
}
__global__ void k_count_deg(const int* __restrict__ ei) {
    int e = blockIdx.x * blockDim.x + threadIdx.x;
    if (e < NEDGES) atomicAdd(&g_deg[ei[NEDGES + e]], 1);
}
__global__ void __launch_bounds__(1024) k_scan() {
    __shared__ int warp_sums[32];
    __shared__ int s_carry;
    const int tid = threadIdx.x, lane = tid & 31, w = tid >> 5;
    if (tid == 0) s_carry = 0;
    __syncthreads();
    for (int base = 0; base < NNODES; base += 1024) {
        int i = base + tid;
        int d = (i < NNODES) ? g_deg[i] : 0;
        int v = d;
#pragma unroll
        for (int o = 1; o < 32; o <<= 1) {
            int t = __shfl_up_sync(~0u, v, o);
            if (lane >= o) v += t;
        }
        if (lane == 31) warp_sums[w] = v;
        __syncthreads();
        if (w == 0) {
            int s = warp_sums[lane];
#pragma unroll
            for (int o = 1; o < 32; o <<= 1) {
                int t = __shfl_up_sync(~0u, s, o);
                if (lane >= o) s += t;
            }
            warp_sums[lane] = s;
        }
        __syncthreads();
        int excl = v - d + (w > 0 ? warp_sums[w - 1] : 0) + s_carry;
        if (i < NNODES) {
            g_rowstart[i] = excl;
            g_cursor[i]   = excl;
            g_invdeg[i]   = 1.0f / fmaxf((float)d, 1.0f);
        }
        __syncthreads();
        if (tid == 1023) s_carry = excl + d;
        __syncthreads();
    }
}
__global__ void k_fill_csr(const int* __restrict__ ei) {
    int e = blockIdx.x * blockDim.x + threadIdx.x;
    if (e >= NEDGES) return;
    int src = ei[e];
    int dst = ei[NEDGES + e];
    int slot = atomicAdd(&g_cursor[dst], 1);
    g_csrc[slot] = src;
}

// ---------------------------------------------------------------------------
// fp16 hi/lo split helpers
// ---------------------------------------------------------------------------
__device__ __forceinline__ void split_store(float v0, float v1,
                                            __half* hi, __half* lo) {
    __half h0 = __float2half_rn(v0), h1 = __float2half_rn(v1);
    *(__half2*)hi = __halves2half2(h0, h1);
    *(__half2*)lo = __halves2half2(__float2half_rn(v0 - __half2float(h0)),
                                   __float2half_rn(v1 - __half2float(h1)));
}

// Gather (layer 1): fp32 source. One warp per node, 4 feats/lane.
__global__ void __launch_bounds__(256) k_gather_f32(const float* __restrict__ in) {
    int node = (blockIdx.x * blockDim.x + threadIdx.x) >> 5;
    int lane = threadIdx.x & 31;
    if (node >= NNODES) return;
    int start = g_rowstart[node];
    int deg = g_deg[node];
    const int* lst = g_csrc + start;
    float4 a0 = make_float4(0.f, 0.f, 0.f, 0.f);
    float4 a1 = make_float4(0.f, 0.f, 0.f, 0.f);
    int j = 0;
    for (; j + 2 <= deg; j += 2) {
        float4 v0 = *(const float4*)(in + (size_t)lst[j] * DF + lane * 4);
        float4 v1 = *(const float4*)(in + (size_t)lst[j + 1] * DF + lane * 4);
        a0.x += v0.x; a0.y += v0.y; a0.z += v0.z; a0.w += v0.w;
        a1.x += v1.x; a1.y += v1.y; a1.z += v1.z; a1.w += v1.w;
    }
    if (j < deg) {
        float4 v0 = *(const float4*)(in + (size_t)lst[j] * DF + lane * 4);
        a0.x += v0.x; a0.y += v0.y; a0.z += v0.z; a0.w += v0.w;
    }
    float s = g_invdeg[node];
    size_t o = (size_t)node * DF + lane * 4;
    split_store((a0.x + a1.x) * s, (a0.y + a1.y) * s, g_aghi + o, g_aglo + o);
    split_store((a0.z + a1.z) * s, (a0.w + a1.w) * s, g_aghi + o + 2, g_aglo + o + 2);
}

// Gather (layers 2-3): fp16 hi/lo pair source (reconstruct hi+lo in fp32).
__global__ void __launch_bounds__(256) k_gather_h() {
    int node = (blockIdx.x * blockDim.x + threadIdx.x) >> 5;
    int lane = threadIdx.x & 31;
    if (node >= NNODES) return;
    int start = g_rowstart[node];
    int deg = g_deg[node];
    const int* lst = g_csrc + start;
    float4 acc = make_float4(0.f, 0.f, 0.f, 0.f);
    for (int j = 0; j < deg; ++j) {
        size_t o = (size_t)lst[j] * DF + lane * 4;
        __half2 h0 = *(const __half2*)(g_xhi + o);
        __half2 h1 = *(const __half2*)(g_xhi + o + 2);
        __half2 l0 = *(const __half2*)(g_xlo + o);
        __half2 l1 = *(const __half2*)(g_xlo + o + 2);
        float2 f0 = __half22float2(h0), f1 = __half22float2(h1);
        float2 g0 = __half22float2(l0), g1 = __half22float2(l1);
        acc.x += f0.x + g0.x; acc.y += f0.y + g0.y;
        acc.z += f1.x + g1.x; acc.w += f1.y + g1.y;
    }
    float s = g_invdeg[node];
    size_t o = (size_t)node * DF + lane * 4;
    split_store(acc.x * s, acc.y * s, g_aghi + o, g_aglo + o);
    split_store(acc.z * s, acc.w * s, g_aghi + o + 2, g_aglo + o + 2);
}

// fp32 x -> fp16 hi/lo (layer-1 self operand)
__global__ void k_split_x(const float4* __restrict__ in) {
    int i = blockIdx.x * blockDim.x + threadIdx.x;
    if (i >= (NNODES * DF) / 4) return;
    float4 v = in[i];
    size_t o = (size_t)i * 4;
    split_store(v.x, v.y, g_xhi + o, g_xlo + o);
    split_store(v.z, v.w, g_xhi + o + 2, g_xlo + o + 2);
}

// All six W [K=128][N] fp32 -> W^T [N][K=128] fp16
__global__ void k_w_prep_all(const float* __restrict__ Wl1, const float* __restrict__ Wr1,
                             const float* __restrict__ Wl2, const float* __restrict__ Wr2,
                             const float* __restrict__ Wl3, const float* __restrict__ Wr3) {
    int i = blockIdx.x * blockDim.x + threadIdx.x;
    if (i >= 81920) return;
    const float* W;
    int N, li;
    if (i < 32768) { N = 128; if (i < 16384) { W = Wl1; li = i; } else { W = Wr1; li = i - 16384; } }
    else if (i < 65536) { N = 128; if (i < 49152) { W = Wl2; li = i - 32768; } else { W = Wr2; li = i - 49152; } }
    else { N = 64; if (i < 73728) { W = Wl3; li = i - 65536; } else { W = Wr3; li = i - 73728; } }
    int n = li >> 7, k = li & 127;
    g_w[i] = __float2half_rn(W[k * N + n]);
}

// ---------------------------------------------------------------------------
// Pipelined fp16 GEMM (2-term compensated):
//   D = Xhi@Wl + Xlo@Wl + Ahi@Wr + Alo@Wr   (8 K=64 segments)
// B (Wl^T|Wr^T, full K=128) resident in SMEM; A double-buffered via cp.async.
// CTA: 128 x TN, 256 thr = 8 warps (2m x 4n).
// ---------------------------------------------------------------------------
#define ROWA 72    // A SMEM row stride (elements)
#define ROWB 136   // B SMEM row stride (elements)

template<int TN, bool RELU, bool SPLIT>
__global__ void __launch_bounds__(256, 2)
k_gemm_mma(const __half* __restrict__ bl, const __half* __restrict__ br,
           const float* __restrict__ bias, float* __restrict__ outF) {
    extern __shared__ __align__(16) __half smem[];
    constexpr int NTC = TN / 4;
    constexpr int NP  = NTC / 16;
    constexpr int NT  = NTC / 8;

    const int tid = threadIdx.x;
    const int lane = tid & 31, wid = tid >> 5;
    const int warp_m = wid >> 2, warp_n = wid & 3;
    const int m0 = blockIdx.x * 128;

    const uint32_t aBase = smem_u32(smem);                   // 2 stages x 128 x ROWA
    const uint32_t bBase = aBase + 2u * 128 * ROWA * 2;      // 2*TN rows x ROWB
    __half* bSm = smem + 2 * 128 * ROWA;

    const int aLaneOff = (warp_m * 64 + (lane & 15)) * ROWA + (lane >> 4) * 8;
    const int bLaneOff = (warp_n * NTC + (lane & 7) + ((lane >> 4) & 1) * 8) * ROWB
                       + ((lane >> 3) & 1) * 8;

    const __half* aPtr[4] = {g_xhi, g_xlo, g_aghi, g_aglo};
    constexpr int aSel[8] = {0, 1, 0, 1, 2, 3, 2, 3};
    constexpr int kOff[8] = {0, 0, 64, 64, 0, 0, 64, 64};
    constexpr int mSel[8] = {0, 0, 0, 0, 1, 1, 1, 1};

    // ---- A stage issue (cp.async): 128 rows x 64 halves = 1024 x 16B ----
    auto issueA = [&](int s, int buf) {
        const __half* ap = aPtr[aSel[s]] + kOff[s];
        uint32_t dst0 = aBase + (uint32_t)buf * 128 * ROWA * 2;
#pragma unroll
        for (int i = 0; i < 4; ++i) {
            int idx = tid + i * 256;
            int row = idx >> 3, q = idx & 7;
            int grow = m0 + row;
            if (grow > NNODES - 1) grow = NNODES - 1;   // clamp: garbage rows unused
            cpa16(dst0 + (uint32_t)(row * ROWA + q * 8) * 2,
                  ap + (size_t)grow * DF + q * 8);
        }
    };

    // ---- Prologue: B resident (2*TN rows x 128 halves) + A stages 0,1 ----
    {
#pragma unroll
        for (int i = 0; i < (2 * TN * 16) / 256; ++i) {
            int idx = tid + i * 256;
            int row = idx >> 4, q = idx & 15;
            const __half* src = (row < TN ? bl + (size_t)row * DF
                                          : br + (size_t)(row - TN) * DF) + q * 8;
            cpa16(bBase + (uint32_t)(row * ROWB + q * 8) * 2, src);
        }
        issueA(0, 0);
        CPA_COMMIT();          // g0: B + A0
        issueA(1, 1);
        CPA_COMMIT();          // g1: A1
    }

    float acc[4][NT][4];
#pragma unroll
    for (int mt = 0; mt < 4; ++mt)
#pragma unroll
        for (int nt = 0; nt < NT; ++nt)
#pragma unroll
            for (int r = 0; r < 4; ++r) acc[mt][nt][r] = 0.f;

#pragma unroll
    for (int s = 0; s < 8; ++s) {
        if (s < 7) { CPA_WAIT(1); } else { CPA_WAIT(0); }
        __syncthreads();

        const uint32_t aB = aBase + (uint32_t)(s & 1) * 128 * ROWA * 2;
        const int bOff = mSel[s] * TN * ROWB + kOff[s];
#pragma unroll
        for (int kk = 0; kk < 4; ++kk) {
            uint32_t a[4][4];
#pragma unroll
            for (int mt = 0; mt < 4; ++mt)
                ldm4(a[mt], aB + 2u * (aLaneOff + mt * 16 * ROWA + kk * 16));
            uint32_t b[NP][4];
#pragma unroll
            for (int np = 0; np < NP; ++np)
                ldm4(b[np], bBase + 2u * (bOff + bLaneOff + np * 16 * ROWB + kk * 16));
#pragma unroll
            for (int mt = 0; mt < 4; ++mt)
#pragma unroll
                for (int np = 0; np < NP; ++np) {
                    mma16816(acc[mt][np * 2 + 0], a[mt], b[np][0], b[np][1]);
                    mma16816(acc[mt][np * 2 + 1], a[mt], b[np][2], b[np][3]);
                }
        }
        __syncthreads();
        if (s + 2 < 8) { issueA(s + 2, s & 1); CPA_COMMIT(); }
    }

    // ---- Epilogue ----
#pragma unroll
    for (int mt = 0; mt < 4; ++mt) {
        int row0 = m0 + warp_m * 64 + mt * 16 + (lane >> 2);
#pragma unroll
        for (int nt = 0; nt < NT; ++nt) {
            int col = warp_n * NTC + nt * 8 + (lane & 3) * 2;
            float bx = bias[col], by = bias[col + 1];
#pragma unroll
            for (int half = 0; half < 2; ++half) {
                int row = row0 + half * 8;
                if (row >= NNODES) continue;
                float v0 = acc[mt][nt][half * 2 + 0] + bx;
                float v1 = acc[mt][nt][half * 2 + 1] + by;
                if (RELU) { v0 = fmaxf(v0, 0.f); v1 = fmaxf(v1, 0.f); }
                if (SPLIT) {
                    split_store(v0, v1, g_xhi + (size_t)row * TN + col,
                                g_xlo + (size_t)row * TN + col);
                } else {
                    *(float2*)(outF + (size_t)row * TN + col) = make_float2(v0, v1);
                }
            }
        }
    }
}

// ---------------------------------------------------------------------------
// Launch
// ---------------------------------------------------------------------------
extern "C" void kernel_launch(void* const* d_in, const int* in_sizes, int n_in,
                              void* d_out, int out_size) {
    const float* x   = (const float*)d_in[0];
    const int*   ei  = (const int*)d_in[1];
    const float* Wl1 = (const float*)d_in[2];
    const float* Wr1 = (const float*)d_in[3];
    const float* b1  = (const float*)d_in[4];
    const float* Wl2 = (const float*)d_in[5];
    const float* Wr2 = (const float*)d_in[6];
    const float* b2  = (const float*)d_in[7];
    const float* Wl3 = (const float*)d_in[8];
    const float* Wr3 = (const float*)d_in[9];
    const float* b3  = (const float*)d_in[10];
    float* out = (float*)d_out;

    __half* w = nullptr;
    cudaGetSymbolAddress((void**)&w, g_w);

    const int ZB = 256;
    const int nodeBlocks = (NNODES + ZB - 1) / ZB;
    const int edgeBlocks = (NEDGES + ZB - 1) / ZB;
    const int featBlocks = ((NNODES * DF) / 4 + ZB - 1) / ZB;
    const int gathBlocks = (NNODES * 32 + ZB - 1) / ZB;     // 6250
    const int gemmBlocks = (NNODES + 127) / 128;            // 391
    const int wBlocks    = (81920 + ZB - 1) / ZB;
    const int SMEM128 = (2 * 128 * ROWA + 2 * 128 * ROWB) * 2;   // 106496
    const int SMEM64  = (2 * 128 * ROWA + 2 * 64 * ROWB) * 2;    //  71680

    cudaFuncSetAttribute(k_gemm_mma<128, true, true>,
                         cudaFuncAttributeMaxDynamicSharedMemorySize, SMEM128);
    cudaFuncSetAttribute(k_gemm_mma<64, false, false>,
                         cudaFuncAttributeMaxDynamicSharedMemorySize, SMEM64);

    // CSR build (once per launch)
    k_zero_deg<<<nodeBlocks, ZB>>>();
    k_count_deg<<<edgeBlocks, ZB>>>(ei);
    k_scan<<<1, 1024>>>();
    k_fill_csr<<<edgeBlocks, ZB>>>(ei);

    // Operand prep
    k_w_prep_all<<<wBlocks, ZB>>>(Wl1, Wr1, Wl2, Wr2, Wl3, Wr3);
    k_split_x<<<featBlocks, ZB>>>((const float4*)x);

    // ---- Layer 1 ----
    k_gather_f32<<<gathBlocks, ZB>>>(x);
    k_gemm_mma<128, true, true><<<gemmBlocks, 256, SMEM128>>>(
        w + W_L1L, w + W_L1R, b1, nullptr);

    // ---- Layer 2 ----
    k_gather_h<<<gathBlocks, ZB>>>();
    k_gemm_mma<128, true, true><<<gemmBlocks, 256, SMEM128>>>(
        w + W_L2L, w + W_L2R, b2, nullptr);

    // ---- Layer 3 (N=64, no relu, fp32 out) ----
    k_gather_h<<<gathBlocks, ZB>>>();
    k_gemm_mma<64, false, false><<<gemmBlocks, 256, SMEM64>>>(
        w + W_L3L, w + W_L3R, b3, out);
}

// round 7
// speedup vs baseline: 2.7158x; 1.5895x over previous
#include <cuda_runtime.h>
#include <cuda_fp16.h>
#include <cstdint>

#define NNODES 50000
#define NEDGES 800000
#define DF     128

// ---------------------------------------------------------------------------
// Scratch (__device__ globals; no allocations allowed)
// ---------------------------------------------------------------------------
__device__ __align__(16) __half g_xhi[NNODES * DF];   // self operand hi (layer output)
__device__ __align__(16) __half g_xlo[NNODES * DF];   // self operand lo
__device__ __align__(16) __half g_aghi[NNODES * DF];  // normalized agg hi
__device__ __align__(16) __half g_aglo[NNODES * DF];  // normalized agg lo
__device__ __align__(16) __half g_w[81920];           // all W^T fp16 (6 mats)
__device__ float g_invdeg[NNODES];
__device__ int   g_deg[NNODES];
__device__ int   g_rowstart[NNODES];
__device__ int   g_cursor[NNODES];
__device__ int   g_csrc[NEDGES];

// Weight buffer offsets (fp16 elements), layout [N][K=128]
#define W_L1L 0
#define W_L1R 16384
#define W_L2L 32768
#define W_L2R 49152
#define W_L3L 65536
#define W_L3R 73728

__device__ __forceinline__ uint32_t smem_u32(const void* p) {
    uint32_t a;
    asm("{ .reg .u64 t; cvta.to.shared.u64 t, %1; cvt.u32.u64 %0, t; }"
        : "=r"(a) : "l"(p));
    return a;
}
__device__ __forceinline__ void ldm4(uint32_t* r, uint32_t addr) {
    asm volatile("ldmatrix.sync.aligned.m8n8.x4.shared.b16 {%0,%1,%2,%3}, [%4];"
                 : "=r"(r[0]), "=r"(r[1]), "=r"(r[2]), "=r"(r[3]) : "r"(addr));
}
__device__ __forceinline__ void mma16816(float* c, const uint32_t* a,
                                         uint32_t b0, uint32_t b1) {
    asm volatile(
        "mma.sync.aligned.m16n8k16.row.col.f32.f16.f16.f32 "
        "{%0,%1,%2,%3}, {%4,%5,%6,%7}, {%8,%9}, {%0,%1,%2,%3};"
        : "+f"(c[0]), "+f"(c[1]), "+f"(c[2]), "+f"(c[3])
        : "r"(a[0]), "r"(a[1]), "r"(a[2]), "r"(a[3]), "r"(b0), "r"(b1));
}
__device__ __forceinline__ void cpa16(uint32_t dst, const void* src) {
    asm volatile("cp.async.cg.shared.global [%0], [%1], 16;" :: "r"(dst), "l"(src));
}
#define CPA_COMMIT() asm volatile("cp.async.commit_group;" ::: "memory")
#define CPA_WAIT(n)  asm volatile("cp.async.wait_group %0;" :: "n"(n) : "memory")

// ---------------------------------------------------------------------------
// CSR build
// ---------------------------------------------------------------------------
__global__ void k_zero_deg() {
    int i = blockIdx.x * blockDim.x + threadIdx.x;
    if (i < NNODES) g_deg[i] = 0;
}
__global__ void k_count_deg(const int* __restrict__ ei) {
    int e = blockIdx.x * blockDim.x + threadIdx.x;
    if (e < NEDGES) atomicAdd(&g_deg[ei[NEDGES + e]], 1);
}
__global__ void __launch_bounds__(1024) k_scan() {
    __shared__ int warp_sums[32];
    __shared__ int s_carry;
    const int tid = threadIdx.x, lane = tid & 31, w = tid >> 5;
    if (tid == 0) s_carry = 0;
    __syncthreads();
    for (int base = 0; base < NNODES; base += 1024) {
        int i = base + tid;
        int d = (i < NNODES) ? g_deg[i] : 0;
        int v = d;
#pragma unroll
        for (int o = 1; o < 32; o <<= 1) {
            int t = __shfl_up_sync(~0u, v, o);
            if (lane >= o) v += t;
        }
        if (lane == 31) warp_sums[w] = v;
        __syncthreads();
        if (w == 0) {
            int s = warp_sums[lane];
#pragma unroll
            for (int o = 1; o < 32; o <<= 1) {
                int t = __shfl_up_sync(~0u, s, o);
                if (lane >= o) s += t;
            }
            warp_sums[lane] = s;
        }
        __syncthreads();
        int excl = v - d + (w > 0 ? warp_sums[w - 1] : 0) + s_carry;
        if (i < NNODES) {
            g_rowstart[i] = excl;
            g_cursor[i]   = excl;
            g_invdeg[i]   = 1.0f / fmaxf((float)d, 1.0f);
        }
        __syncthreads();
        if (tid == 1023) s_carry = excl + d;
        __syncthreads();
    }
}
__global__ void k_fill_csr(const int* __restrict__ ei) {
    int e = blockIdx.x * blockDim.x + threadIdx.x;
    if (e >= NEDGES) return;
    int src = ei[e];
    int dst = ei[NEDGES + e];
    int slot = atomicAdd(&g_cursor[dst], 1);
    g_csrc[slot] = src;
}

// ---------------------------------------------------------------------------
// fp16 hi/lo split helper
// ---------------------------------------------------------------------------
__device__ __forceinline__ void split_store(float v0, float v1,
                                            __half* hi, __half* lo) {
    __half h0 = __float2half_rn(v0), h1 = __float2half_rn(v1);
    *(__half2*)hi = __halves2half2(h0, h1);
    *(__half2*)lo = __halves2half2(__float2half_rn(v0 - __half2float(h0)),
                                   __float2half_rn(v1 - __half2float(h1)));
}

// ---------------------------------------------------------------------------
// Gather-aggregate (all layers): neighbor mean over the fp16 hi representation.
// One warp per node; 4 feats/lane (one 8B load per neighbor per lane);
// 4-way unrolled with independent accumulators; result split hi/lo for MMA.
// ---------------------------------------------------------------------------
__global__ void __launch_bounds__(256) k_gather_h() {
    int node = (blockIdx.x * blockDim.x + threadIdx.x) >> 5;
    int lane = threadIdx.x & 31;
    if (node >= NNODES) return;
    int start = g_rowstart[node];
    int deg = g_deg[node];
    const int* lst = g_csrc + start;
    const int fo = lane * 4;   // feature offset for this lane

    float4 a0 = make_float4(0.f, 0.f, 0.f, 0.f);
    float4 a1 = make_float4(0.f, 0.f, 0.f, 0.f);
    float4 a2 = make_float4(0.f, 0.f, 0.f, 0.f);
    float4 a3 = make_float4(0.f, 0.f, 0.f, 0.f);

    int j = 0;
    for (; j + 4 <= deg; j += 4) {
        uint2 u0 = *(const uint2*)(g_xhi + (size_t)lst[j]     * DF + fo);
        uint2 u1 = *(const uint2*)(g_xhi + (size_t)lst[j + 1] * DF + fo);
        uint2 u2 = *(const uint2*)(g_xhi + (size_t)lst[j + 2] * DF + fo);
        uint2 u3 = *(const uint2*)(g_xhi + (size_t)lst[j + 3] * DF + fo);
        float2 p, q;
        p = __half22float2(*(__half2*)&u0.x); q = __half22float2(*(__half2*)&u0.y);
        a0.x += p.x; a0.y += p.y; a0.z += q.x; a0.w += q.y;
        p = __half22float2(*(__half2*)&u1.x); q = __half22float2(*(__half2*)&u1.y);
        a1.x += p.x; a1.y += p.y; a1.z += q.x; a1.w += q.y;
        p = __half22float2(*(__half2*)&u2.x); q = __half22float2(*(__half2*)&u2.y);
        a2.x += p.x; a2.y += p.y; a2.z += q.x; a2.w += q.y;
        p = __half22float2(*(__half2*)&u3.x); q = __half22float2(*(__half2*)&u3.y);
        a3.x += p.x; a3.y += p.y; a3.z += q.x; a3.w += q.y;
    }
    for (; j < deg; ++j) {
        uint2 u0 = *(const uint2*)(g_xhi + (size_t)lst[j] * DF + fo);
        float2 p = __half22float2(*(__half2*)&u0.x);
        float2 q = __half22float2(*(__half2*)&u0.y);
        a0.x += p.x; a0.y += p.y; a0.z += q.x; a0.w += q.y;
    }
    float s = g_invdeg[node];
    float vx = (a0.x + a1.x + a2.x + a3.x) * s;
    float vy = (a0.y + a1.y + a2.y + a3.y) * s;
    float vz = (a0.z + a1.z + a2.z + a3.z) * s;
    float vw = (a0.w + a1.w + a2.w + a3.w) * s;

    size_t o = (size_t)node * DF + fo;
    split_store(vx, vy, g_aghi + o, g_aglo + o);
    split_store(vz, vw, g_aghi + o + 2, g_aglo + o + 2);
}

// fp32 x -> fp16 hi/lo (layer-1 self operand; also the gather source for L1)
__global__ void k_split_x(const float4* __restrict__ in) {
    int i = blockIdx.x * blockDim.x + threadIdx.x;
    if (i >= (NNODES * DF) / 4) return;
    float4 v = in[i];
    size_t o = (size_t)i * 4;
    split_store(v.x, v.y, g_xhi + o, g_xlo + o);
    split_store(v.z, v.w, g_xhi + o + 2, g_xlo + o + 2);
}

// All six W [K=128][N] fp32 -> W^T [N][K=128] fp16
__global__ void k_w_prep_all(const float* __restrict__ Wl1, const float* __restrict__ Wr1,
                             const float* __restrict__ Wl2, const float* __restrict__ Wr2,
                             const float* __restrict__ Wl3, const float* __restrict__ Wr3) {
    int i = blockIdx.x * blockDim.x + threadIdx.x;
    if (i >= 81920) return;
    const float* W;
    int N, li;
    if (i < 32768) { N = 128; if (i < 16384) { W = Wl1; li = i; } else { W = Wr1; li = i - 16384; } }
    else if (i < 65536) { N = 128; if (i < 49152) { W = Wl2; li = i - 32768; } else { W = Wr2; li = i - 49152; } }
    else { N = 64; if (i < 73728) { W = Wl3; li = i - 65536; } else { W = Wr3; li = i - 73728; } }
    int n = li >> 7, k = li & 127;
    g_w[i] = __float2half_rn(W[k * N + n]);
}

// ---------------------------------------------------------------------------
// Pipelined fp16 GEMM (2-term compensated):
//   D = Xhi@Wl + Xlo@Wl + Ahi@Wr + Alo@Wr   (8 K=64 segments)
// B (Wl^T|Wr^T, full K=128) resident in SMEM; A double-buffered via cp.async.
// CTA: 128 x TN, 256 thr = 8 warps (2m x 4n).
// ---------------------------------------------------------------------------
#define ROWA 72    // A SMEM row stride (elements)
#define ROWB 136   // B SMEM row stride (elements)

template<int TN, bool RELU, bool SPLIT>
__global__ void __launch_bounds__(256, 2)
k_gemm_mma(const __half* __restrict__ bl, const __half* __restrict__ br,
           const float* __restrict__ bias, float* __restrict__ outF) {
    extern __shared__ __align__(16) __half smem[];
    constexpr int NTC = TN / 4;
    constexpr int NP  = NTC / 16;
    constexpr int NT  = NTC / 8;

    const int tid = threadIdx.x;
    const int lane = tid & 31, wid = tid >> 5;
    const int warp_m = wid >> 2, warp_n = wid & 3;
    const int m0 = blockIdx.x * 128;

    const uint32_t aBase = smem_u32(smem);                   // 2 stages x 128 x ROWA
    const uint32_t bBase = aBase + 2u * 128 * ROWA * 2;      // 2*TN rows x ROWB

    const int aLaneOff = (warp_m * 64 + (lane & 15)) * ROWA + (lane >> 4) * 8;
    const int bLaneOff = (warp_n * NTC + (lane & 7) + ((lane >> 4) & 1) * 8) * ROWB
                       + ((lane >> 3) & 1) * 8;

    const __half* aPtr[4] = {g_xhi, g_xlo, g_aghi, g_aglo};
    constexpr int aSel[8] = {0, 1, 0, 1, 2, 3, 2, 3};
    constexpr int kOff[8] = {0, 0, 64, 64, 0, 0, 64, 64};
    constexpr int mSel[8] = {0, 0, 0, 0, 1, 1, 1, 1};

    auto issueA = [&](int s, int buf) {
        const __half* ap = aPtr[aSel[s]] + kOff[s];
        uint32_t dst0 = aBase + (uint32_t)buf * 128 * ROWA * 2;
#pragma unroll
        for (int i = 0; i < 4; ++i) {
            int idx = tid + i * 256;
            int row = idx >> 3, q = idx & 7;
            int grow = m0 + row;
            if (grow > NNODES - 1) grow = NNODES - 1;   // clamp: garbage rows unused
            cpa16(dst0 + (uint32_t)(row * ROWA + q * 8) * 2,
                  ap + (size_t)grow * DF + q * 8);
        }
    };

    {
#pragma unroll
        for (int i = 0; i < (2 * TN * 16) / 256; ++i) {
            int idx = tid + i * 256;
            int row = idx >> 4, q = idx & 15;
            const __half* src = (row < TN ? bl + (size_t)row * DF
                                          : br + (size_t)(row - TN) * DF) + q * 8;
            cpa16(bBase + (uint32_t)(row * ROWB + q * 8) * 2, src);
        }
        issueA(0, 0);
        CPA_COMMIT();          // g0: B + A0
        issueA(1, 1);
        CPA_COMMIT();          // g1: A1
    }

    float acc[4][NT][4];
#pragma unroll
    for (int mt = 0; mt < 4; ++mt)
#pragma unroll
        for (int nt = 0; nt < NT; ++nt)
#pragma unroll
            for (int r = 0; r < 4; ++r) acc[mt][nt][r] = 0.f;

#pragma unroll
    for (int s = 0; s < 8; ++s) {
        if (s < 7) { CPA_WAIT(1); } else { CPA_WAIT(0); }
        __syncthreads();

        const uint32_t aB = aBase + (uint32_t)(s & 1) * 128 * ROWA * 2;
        const int bOff = mSel[s] * TN * ROWB + kOff[s];
#pragma unroll
        for (int kk = 0; kk < 4; ++kk) {
            uint32_t a[4][4];
#pragma unroll
            for (int mt = 0; mt < 4; ++mt)
                ldm4(a[mt], aB + 2u * (aLaneOff + mt * 16 * ROWA + kk * 16));
            uint32_t b[NP][4];
#pragma unroll
            for (int np = 0; np < NP; ++np)
                ldm4(b[np], bBase + 2u * (bOff + bLaneOff + np * 16 * ROWB + kk * 16));
#pragma unroll
            for (int mt = 0; mt < 4; ++mt)
#pragma unroll
                for (int np = 0; np < NP; ++np) {
                    mma16816(acc[mt][np * 2 + 0], a[mt], b[np][0], b[np][1]);
                    mma16816(acc[mt][np * 2 + 1], a[mt], b[np][2], b[np][3]);
                }
        }
        __syncthreads();
        if (s + 2 < 8) { issueA(s + 2, s & 1); CPA_COMMIT(); }
    }

#pragma unroll
    for (int mt = 0; mt < 4; ++mt) {
        int row0 = m0 + warp_m * 64 + mt * 16 + (lane >> 2);
#pragma unroll
        for (int nt = 0; nt < NT; ++nt) {
            int col = warp_n * NTC + nt * 8 + (lane & 3) * 2;
            float bx = bias[col], by = bias[col + 1];
#pragma unroll
            for (int half = 0; half < 2; ++half) {
                int row = row0 + half * 8;
                if (row >= NNODES) continue;
                float v0 = acc[mt][nt][half * 2 + 0] + bx;
                float v1 = acc[mt][nt][half * 2 + 1] + by;
                if (RELU) { v0 = fmaxf(v0, 0.f); v1 = fmaxf(v1, 0.f); }
                if (SPLIT) {
                    split_store(v0, v1, g_xhi + (size_t)row * TN + col,
                                g_xlo + (size_t)row * TN + col);
                } else {
                    *(float2*)(outF + (size_t)row * TN + col) = make_float2(v0, v1);
                }
            }
        }
    }
}

// ---------------------------------------------------------------------------
// Launch
// ---------------------------------------------------------------------------
extern "C" void kernel_launch(void* const* d_in, const int* in_sizes, int n_in,
                              void* d_out, int out_size) {
    const float* x   = (const float*)d_in[0];
    const int*   ei  = (const int*)d_in[1];
    const float* Wl1 = (const float*)d_in[2];
    const float* Wr1 = (const float*)d_in[3];
    const float* b1  = (const float*)d_in[4];
    const float* Wl2 = (const float*)d_in[5];
    const float* Wr2 = (const float*)d_in[6];
    const float* b2  = (const float*)d_in[7];
    const float* Wl3 = (const float*)d_in[8];
    const float* Wr3 = (const float*)d_in[9];
    const float* b3  = (const float*)d_in[10];
    float* out = (float*)d_out;

    __half* w = nullptr;
    cudaGetSymbolAddress((void**)&w, g_w);

    const int ZB = 256;
    const int nodeBlocks = (NNODES + ZB - 1) / ZB;
    const int edgeBlocks = (NEDGES + ZB - 1) / ZB;
    const int featBlocks = ((NNODES * DF) / 4 + ZB - 1) / ZB;
    const int gathBlocks = (NNODES * 32 + ZB - 1) / ZB;     // 6250
    const int gemmBlocks = (NNODES + 127) / 128;            // 391
    const int wBlocks    = (81920 + ZB - 1) / ZB;
    const int SMEM128 = (2 * 128 * ROWA + 2 * 128 * ROWB) * 2;   // 106496
    const int SMEM64  = (2 * 128 * ROWA + 2 * 64 * ROWB) * 2;    //  71680

    cudaFuncSetAttribute(k_gemm_mma<128, true, true>,
                         cudaFuncAttributeMaxDynamicSharedMemorySize, SMEM128);
    cudaFuncSetAttribute(k_gemm_mma<64, false, false>,
                         cudaFuncAttributeMaxDynamicSharedMemorySize, SMEM64);

    // CSR build (once per launch)
    k_zero_deg<<<nodeBlocks, ZB>>>();
    k_count_deg<<<edgeBlocks, ZB>>>(ei);
    k_scan<<<1, 1024>>>();
    k_fill_csr<<<edgeBlocks, ZB>>>(ei);

    // Operand prep (split_x must precede layer-1 gather: gather reads g_xhi)
    k_w_prep_all<<<wBlocks, ZB>>>(Wl1, Wr1, Wl2, Wr2, Wl3, Wr3);
    k_split_x<<<featBlocks, ZB>>>((const float4*)x);

    // ---- Layer 1 ----
    k_gather_h<<<gathBlocks, ZB>>>();
    k_gemm_mma<128, true, true><<<gemmBlocks, 256, SMEM128>>>(
        w + W_L1L, w + W_L1R, b1, nullptr);

    // ---- Layer 2 ----
    k_gather_h<<<gathBlocks, ZB>>>();
    k_gemm_mma<128, true, true><<<gemmBlocks, 256, SMEM128>>>(
        w + W_L2L, w + W_L2R, b2, nullptr);

    // ---- Layer 3 (N=64, no relu, fp32 out) ----
    k_gather_h<<<gathBlocks, ZB>>>();
    k_gemm_mma<64, false, false><<<gemmBlocks, 256, SMEM64>>>(
        w + W_L3L, w + W_L3R, b3, out);
}

// round 8
// speedup vs baseline: 3.4645x; 1.2757x over previous
#include <cuda_runtime.h>
#include <cuda_fp16.h>
#include <cstdint>

#define NNODES 50000
#define NEDGES 800000
#define DF     128
#define NBLK   196          // ceil(NNODES/256)

// ---------------------------------------------------------------------------
// Scratch (__device__ globals; no allocations allowed)
// ---------------------------------------------------------------------------
__device__ __align__(16) __half g_xhi[NNODES * DF];   // self operand hi (layer output)
__device__ __align__(16) __half g_xlo[NNODES * DF];   // self operand lo
__device__ __align__(16) __half g_aghi[NNODES * DF];  // normalized agg (fp16)
__device__ __align__(16) __half g_w[81920];           // all W^T fp16 (6 mats)
__device__ float g_invdeg[NNODES];
__device__ int   g_deg[NNODES];
__device__ int   g_rowstart[NNODES];
__device__ int   g_cursor[NNODES];
__device__ int   g_csrc[NEDGES];
__device__ int   g_bsum[256];

// Weight buffer offsets (fp16 elements), layout [N][K=128]
#define W_L1L 0
#define W_L1R 16384
#define W_L2L 32768
#define W_L2R 49152
#define W_L3L 65536
#define W_L3R 73728

__device__ __forceinline__ uint32_t smem_u32(const void* p) {
    uint32_t a;
    asm("{ .reg .u64 t; cvta.to.shared.u64 t, %1; cvt.u32.u64 %0, t; }"
        : "=r"(a) : "l"(p));
    return a;
}
__device__ __forceinline__ void ldm4(uint32_t* r, uint32_t addr) {
    asm volatile("ldmatrix.sync.aligned.m8n8.x4.shared.b16 {%0,%1,%2,%3}, [%4];"
                 : "=r"(r[0]), "=r"(r[1]), "=r"(r[2]), "=r"(r[3]) : "r"(addr));
}
__device__ __forceinline__ void mma16816(float* c, const uint32_t* a,
                                         uint32_t b0, uint32_t b1) {
    asm volatile(
        "mma.sync.aligned.m16n8k16.row.col.f32.f16.f16.f32 "
        "{%0,%1,%2,%3}, {%4,%5,%6,%7}, {%8,%9}, {%0,%1,%2,%3};"
        : "+f"(c[0]), "+f"(c[1]), "+f"(c[2]), "+f"(c[3])
        : "r"(a[0]), "r"(a[1]), "r"(a[2]), "r"(a[3]), "r"(b0), "r"(b1));
}
__device__ __forceinline__ void cpa16(uint32_t dst, const void* src) {
    asm volatile("cp.async.cg.shared.global [%0], [%1], 16;" :: "r"(dst), "l"(src));
}
#define CPA_COMMIT() asm volatile("cp.async.commit_group;" ::: "memory")
#define CPA_WAIT(n)  asm volatile("cp.async.wait_group %0;" :: "n"(n) : "memory")

// ---------------------------------------------------------------------------
// CSR build
// ---------------------------------------------------------------------------
__global__ void k_zero_deg() {
    int i = blockIdx.x * blockDim.x + threadIdx.x;
    if (i < NNODES) g_deg[i] = 0;
}
// 4 edges per thread (NEDGES % 4 == 0)
__global__ void k_count_deg4(const int* __restrict__ ei) {
    int t = blockIdx.x * blockDim.x + threadIdx.x;
    if (t >= NEDGES / 4) return;
    int4 d = ((const int4*)(ei + NEDGES))[t];
    atomicAdd(&g_deg[d.x], 1);
    atomicAdd(&g_deg[d.y], 1);
    atomicAdd(&g_deg[d.z], 1);
    atomicAdd(&g_deg[d.w], 1);
}
// Per-block exclusive scan of deg -> rowstart (local), block sums -> g_bsum.
__global__ void __launch_bounds__(256) k_scan_a() {
    __shared__ int warp_sums[8];
    const int tid = threadIdx.x, lane = tid & 31, w = tid >> 5;
    int i = blockIdx.x * 256 + tid;
    int d = (i < NNODES) ? g_deg[i] : 0;
    int v = d;
#pragma unroll
    for (int o = 1; o < 32; o <<= 1) {
        int t = __shfl_up_sync(~0u, v, o);
        if (lane >= o) v += t;
    }
    if (lane == 31) warp_sums[w] = v;
    __syncthreads();
    if (w == 0 && lane < 8) {
        int s = warp_sums[lane];
#pragma unroll
        for (int o = 1; o < 8; o <<= 1) {
            int t = __shfl_up_sync(0xFF, s, o);
            if (lane >= o) s += t;
        }
        warp_sums[lane] = s;
    }
    __syncthreads();
    int excl = v - d + (w > 0 ? warp_sums[w - 1] : 0);
    if (i < NNODES) g_rowstart[i] = excl;
    if (tid == 255) g_bsum[blockIdx.x] = excl + d;
}
// Exclusive scan of NBLK block sums (one block).
__global__ void __launch_bounds__(256) k_scan_b() {
    __shared__ int arr[256];
    int tid = threadIdx.x;
    arr[tid] = (tid < NBLK) ? g_bsum[tid] : 0;
    __syncthreads();
#pragma unroll
    for (int o = 1; o < 256; o <<= 1) {
        int t = (tid >= o) ? arr[tid - o] : 0;
        __syncthreads();
        arr[tid] += t;
        __syncthreads();
    }
    if (tid < NBLK) g_bsum[tid] = arr[tid] - ((tid < NBLK) ? 0 : 0) - (tid < NBLK ? g_bsum[tid] : 0) + arr[tid] - arr[tid]; // placeholder, replaced below
}
// NOTE: simpler correct version below (k_scan_b2) is the one launched.
__global__ void __launch_bounds__(256) k_scan_b2() {
    __shared__ int arr[256];
    int tid = threadIdx.x;
    int v = (tid < NBLK) ? g_bsum[tid] : 0;
    arr[tid] = v;
    __syncthreads();
    int acc = v;
#pragma unroll
    for (int o = 1; o < 256; o <<= 1) {
        int t = (tid >= o) ? arr[tid - o] : 0;
        __syncthreads();
        acc += t;
        arr[tid] = acc;
        __syncthreads();
    }
    if (tid < NBLK) g_bsum[tid] = acc - v;   // exclusive
}
// Add block offsets; produce cursor + invdeg.
__global__ void k_scan_c() {
    int i = blockIdx.x * blockDim.x + threadIdx.x;
    if (i >= NNODES) return;
    int rs = g_rowstart[i] + g_bsum[blockIdx.x];
    g_rowstart[i] = rs;
    g_cursor[i] = rs;
    g_invdeg[i] = 1.0f / fmaxf((float)g_deg[i], 1.0f);
}
// 4 edges per thread.
__global__ void k_fill_csr4(const int* __restrict__ ei) {
    int t = blockIdx.x * blockDim.x + threadIdx.x;
    if (t >= NEDGES / 4) return;
    int4 s = ((const int4*)ei)[t];
    int4 d = ((const int4*)(ei + NEDGES))[t];
    int s0 = atomicAdd(&g_cursor[d.x], 1);
    int s1 = atomicAdd(&g_cursor[d.y], 1);
    int s2 = atomicAdd(&g_cursor[d.z], 1);
    int s3 = atomicAdd(&g_cursor[d.w], 1);
    g_csrc[s0] = s.x; g_csrc[s1] = s.y; g_csrc[s2] = s.z; g_csrc[s3] = s.w;
}

// ---------------------------------------------------------------------------
// fp16 hi/lo split helper
// ---------------------------------------------------------------------------
__device__ __forceinline__ void split_store(float v0, float v1,
                                            __half* hi, __half* lo) {
    __half h0 = __float2half_rn(v0), h1 = __float2half_rn(v1);
    *(__half2*)hi = __halves2half2(h0, h1);
    *(__half2*)lo = __halves2half2(__float2half_rn(v0 - __half2float(h0)),
                                   __float2half_rn(v1 - __half2float(h1)));
}

// ---------------------------------------------------------------------------
// Gather-aggregate: neighbor mean over fp16 hi; one warp per node, 4 feats/lane.
// Result written as plain fp16 (no lo compensation on agg).
// ---------------------------------------------------------------------------
__global__ void __launch_bounds__(256) k_gather_h() {
    int node = (blockIdx.x * blockDim.x + threadIdx.x) >> 5;
    int lane = threadIdx.x & 31;
    if (node >= NNODES) return;
    int start = g_rowstart[node];
    int deg = g_deg[node];
    const int* lst = g_csrc + start;
    const int fo = lane * 4;

    float4 a0 = make_float4(0.f, 0.f, 0.f, 0.f);
    float4 a1 = make_float4(0.f, 0.f, 0.f, 0.f);
    float4 a2 = make_float4(0.f, 0.f, 0.f, 0.f);
    float4 a3 = make_float4(0.f, 0.f, 0.f, 0.f);

    int j = 0;
    for (; j + 4 <= deg; j += 4) {
        uint2 u0 = *(const uint2*)(g_xhi + (size_t)lst[j]     * DF + fo);
        uint2 u1 = *(const uint2*)(g_xhi + (size_t)lst[j + 1] * DF + fo);
        uint2 u2 = *(const uint2*)(g_xhi + (size_t)lst[j + 2] * DF + fo);
        uint2 u3 = *(const uint2*)(g_xhi + (size_t)lst[j + 3] * DF + fo);
        float2 p, q;
        p = __half22float2(*(__half2*)&u0.x); q = __half22float2(*(__half2*)&u0.y);
        a0.x += p.x; a0.y += p.y; a0.z += q.x; a0.w += q.y;
        p = __half22float2(*(__half2*)&u1.x); q = __half22float2(*(__half2*)&u1.y);
        a1.x += p.x; a1.y += p.y; a1.z += q.x; a1.w += q.y;
        p = __half22float2(*(__half2*)&u2.x); q = __half22float2(*(__half2*)&u2.y);
        a2.x += p.x; a2.y += p.y; a2.z += q.x; a2.w += q.y;
        p = __half22float2(*(__half2*)&u3.x); q = __half22float2(*(__half2*)&u3.y);
        a3.x += p.x; a3.y += p.y; a3.z += q.x; a3.w += q.y;
    }
    for (; j < deg; ++j) {
        uint2 u0 = *(const uint2*)(g_xhi + (size_t)lst[j] * DF + fo);
        float2 p = __half22float2(*(__half2*)&u0.x);
        float2 q = __half22float2(*(__half2*)&u0.y);
        a0.x += p.x; a0.y += p.y; a0.z += q.x; a0.w += q.y;
    }
    float s = g_invdeg[node];
    size_t o = (size_t)node * DF + fo;
    *(__half2*)(g_aghi + o)     = __floats2half2_rn((a0.x + a1.x + a2.x + a3.x) * s,
                                                    (a0.y + a1.y + a2.y + a3.y) * s);
    *(__half2*)(g_aghi + o + 2) = __floats2half2_rn((a0.z + a1.z + a2.z + a3.z) * s,
                                                    (a0.w + a1.w + a2.w + a3.w) * s);
}

// fp32 x -> fp16 hi/lo (layer-1 self operand; also the L1 gather source)
__global__ void k_split_x(const float4* __restrict__ in) {
    int i = blockIdx.x * blockDim.x + threadIdx.x;
    if (i >= (NNODES * DF) / 4) return;
    float4 v = in[i];
    size_t o = (size_t)i * 4;
    split_store(v.x, v.y, g_xhi + o, g_xlo + o);
    split_store(v.z, v.w, g_xhi + o + 2, g_xlo + o + 2);
}

// All six W [K=128][N] fp32 -> W^T [N][K=128] fp16
__global__ void k_w_prep_all(const float* __restrict__ Wl1, const float* __restrict__ Wr1,
                             const float* __restrict__ Wl2, const float* __restrict__ Wr2,
                             const float* __restrict__ Wl3, const float* __restrict__ Wr3) {
    int i = blockIdx.x * blockDim.x + threadIdx.x;
    if (i >= 81920) return;
    const float* W;
    int N, li;
    if (i < 32768) { N = 128; if (i < 16384) { W = Wl1; li = i; } else { W = Wr1; li = i - 16384; } }
    else if (i < 65536) { N = 128; if (i < 49152) { W = Wl2; li = i - 32768; } else { W = Wr2; li = i - 49152; } }
    else { N = 64; if (i < 73728) { W = Wl3; li = i - 65536; } else { W = Wr3; li = i - 73728; } }
    int n = li >> 7, k = li & 127;
    g_w[i] = __float2half_rn(W[k * N + n]);
}

// ---------------------------------------------------------------------------
// Pipelined fp16 GEMM (self compensated, agg plain):
//   D = Xhi@Wl + Xlo@Wl + Ahi@Wr   (6 K=64 segments)
// B (Wl^T|Wr^T) SMEM-resident; A double-buffered via cp.async.
// CTA: 128 x TN, 256 thr = 8 warps (2m x 4n).
// ---------------------------------------------------------------------------
#define ROWA 72
#define ROWB 136
#define NSEG 6

template<int TN, bool RELU, bool SPLIT>
__global__ void __launch_bounds__(256, 2)
k_gemm_mma(const __half* __restrict__ bl, const __half* __restrict__ br,
           const float* __restrict__ bias, float* __restrict__ outF) {
    extern __shared__ __align__(16) __half smem[];
    constexpr int NTC = TN / 4;
    constexpr int NP  = NTC / 16;
    constexpr int NT  = NTC / 8;

    const int tid = threadIdx.x;
    const int lane = tid & 31, wid = tid >> 5;
    const int warp_m = wid >> 2, warp_n = wid & 3;
    const int m0 = blockIdx.x * 128;

    const uint32_t aBase = smem_u32(smem);
    const uint32_t bBase = aBase + 2u * 128 * ROWA * 2;

    const int aLaneOff = (warp_m * 64 + (lane & 15)) * ROWA + (lane >> 4) * 8;
    const int bLaneOff = (warp_n * NTC + (lane & 7) + ((lane >> 4) & 1) * 8) * ROWB
                       + ((lane >> 3) & 1) * 8;

    const __half* aPtr[3] = {g_xhi, g_xlo, g_aghi};
    constexpr int aSel[NSEG] = {0, 1, 0, 1, 2, 2};
    constexpr int kOff[NSEG] = {0, 0, 64, 64, 0, 64};
    constexpr int mSel[NSEG] = {0, 0, 0, 0, 1, 1};

    auto issueA = [&](int s, int buf) {
        const __half* ap = aPtr[aSel[s]] + kOff[s];
        uint32_t dst0 = aBase + (uint32_t)buf * 128 * ROWA * 2;
#pragma unroll
        for (int i = 0; i < 4; ++i) {
            int idx = tid + i * 256;
            int row = idx >> 3, q = idx & 7;
            int grow = m0 + row;
            if (grow > NNODES - 1) grow = NNODES - 1;
            cpa16(dst0 + (uint32_t)(row * ROWA + q * 8) * 2,
                  ap + (size_t)grow * DF + q * 8);
        }
    };

    {
#pragma unroll
        for (int i = 0; i < (2 * TN * 16) / 256; ++i) {
            int idx = tid + i * 256;
            int row = idx >> 4, q = idx & 15;
            const __half* src = (row < TN ? bl + (size_t)row * DF
                                          : br + (size_t)(row - TN) * DF) + q * 8;
            cpa16(bBase + (uint32_t)(row * ROWB + q * 8) * 2, src);
        }
        issueA(0, 0);
        CPA_COMMIT();
        issueA(1, 1);
        CPA_COMMIT();
    }

    float acc[4][NT][4];
#pragma unroll
    for (int mt = 0; mt < 4; ++mt)
#pragma unroll
        for (int nt = 0; nt < NT; ++nt)
#pragma unroll
            for (int r = 0; r < 4; ++r) acc[mt][nt][r] = 0.f;

#pragma unroll
    for (int s = 0; s < NSEG; ++s) {
        if (s < NSEG - 1) { CPA_WAIT(1); } else { CPA_WAIT(0); }
        __syncthreads();

        const uint32_t aB = aBase + (uint32_t)(s & 1) * 128 * ROWA * 2;
        const int bOff = mSel[s] * TN * ROWB + kOff[s];
#pragma unroll
        for (int kk = 0; kk < 4; ++kk) {
            uint32_t a[4][4];
#pragma unroll
            for (int mt = 0; mt < 4; ++mt)
                ldm4(a[mt], aB + 2u * (aLaneOff + mt * 16 * ROWA + kk * 16));
            uint32_t b[NP][4];
#pragma unroll
            for (int np = 0; np < NP; ++np)
                ldm4(b[np], bBase + 2u * (bOff + bLaneOff + np * 16 * ROWB + kk * 16));
#pragma unroll
            for (int mt = 0; mt < 4; ++mt)
#pragma unroll
                for (int np = 0; np < NP; ++np) {
                    mma16816(acc[mt][np * 2 + 0], a[mt], b[np][0], b[np][1]);
                    mma16816(acc[mt][np * 2 + 1], a[mt], b[np][2], b[np][3]);
                }
        }
        __syncthreads();
        if (s + 2 < NSEG) { issueA(s + 2, s & 1); CPA_COMMIT(); }
    }

#pragma unroll
    for (int mt = 0; mt < 4; ++mt) {
        int row0 = m0 + warp_m * 64 + mt * 16 + (lane >> 2);
#pragma unroll
        for (int nt = 0; nt < NT; ++nt) {
            int col = warp_n * NTC + nt * 8 + (lane & 3) * 2;
            float bx = bias[col], by = bias[col + 1];
#pragma unroll
            for (int half = 0; half < 2; ++half) {
                int row = row0 + half * 8;
                if (row >= NNODES) continue;
                float v0 = acc[mt][nt][half * 2 + 0] + bx;
                float v1 = acc[mt][nt][half * 2 + 1] + by;
                if (RELU) { v0 = fmaxf(v0, 0.f); v1 = fmaxf(v1, 0.f); }
                if (SPLIT) {
                    split_store(v0, v1, g_xhi + (size_t)row * TN + col,
                                g_xlo + (size_t)row * TN + col);
                } else {
                    *(float2*)(outF + (size_t)row * TN + col) = make_float2(v0, v1);
                }
            }
        }
    }
}

// ---------------------------------------------------------------------------
// Launch
// ---------------------------------------------------------------------------
extern "C" void kernel_launch(void* const* d_in, const int* in_sizes, int n_in,
                              void* d_out, int out_size) {
    const float* x   = (const float*)d_in[0];
    const int*   ei  = (const int*)d_in[1];
    const float* Wl1 = (const float*)d_in[2];
    const float* Wr1 = (const float*)d_in[3];
    const float* b1  = (const float*)d_in[4];
    const float* Wl2 = (const float*)d_in[5];
    const float* Wr2 = (const float*)d_in[6];
    const float* b2  = (const float*)d_in[7];
    const float* Wl3 = (const float*)d_in[8];
    const float* Wr3 = (const float*)d_in[9];
    const float* b3  = (const float*)d_in[10];
    float* out = (float*)d_out;

    __half* w = nullptr;
    cudaGetSymbolAddress((void**)&w, g_w);

    const int ZB = 256;
    const int nodeBlocks  = (NNODES + ZB - 1) / ZB;         // 196
    const int edge4Blocks = (NEDGES / 4 + ZB - 1) / ZB;     // 782
    const int featBlocks  = ((NNODES * DF) / 4 + ZB - 1) / ZB;
    const int gathBlocks  = (NNODES * 32 + ZB - 1) / ZB;    // 6250
    const int gemmBlocks  = (NNODES + 127) / 128;           // 391
    const int wBlocks     = (81920 + ZB - 1) / ZB;
    const int SMEM128 = (2 * 128 * ROWA + 2 * 128 * ROWB) * 2;   // 106496
    const int SMEM64  = (2 * 128 * ROWA + 2 * 64 * ROWB) * 2;    //  71680

    cudaFuncSetAttribute(k_gemm_mma<128, true, true>,
                         cudaFuncAttributeMaxDynamicSharedMemorySize, SMEM128);
    cudaFuncSetAttribute(k_gemm_mma<64, false, false>,
                         cudaFuncAttributeMaxDynamicSharedMemorySize, SMEM64);

    // CSR build
    k_zero_deg<<<nodeBlocks, ZB>>>();
    k_count_deg4<<<edge4Blocks, ZB>>>(ei);
    k_scan_a<<<nodeBlocks, ZB>>>();
    k_scan_b2<<<1, 256>>>();
    k_scan_c<<<nodeBlocks, ZB>>>();
    k_fill_csr4<<<edge4Blocks, ZB>>>(ei);

    // Operand prep (split_x before layer-1 gather: gather reads g_xhi)
    k_w_prep_all<<<wBlocks, ZB>>>(Wl1, Wr1, Wl2, Wr2, Wl3, Wr3);
    k_split_x<<<featBlocks, ZB>>>((const float4*)x);

    // ---- Layer 1 ----
    k_gather_h<<<gathBlocks, ZB>>>();
    k_gemm_mma<128, true, true><<<gemmBlocks, 256, SMEM128>>>(
        w + W_L1L, w + W_L1R, b1, nullptr);

    // ---- Layer 2 ----
    k_gather_h<<<gathBlocks, ZB>>>();
    k_gemm_mma<128, true, true><<<gemmBlocks, 256, SMEM128>>>(
        w + W_L2L, w + W_L2R, b2, nullptr);

    // ---- Layer 3 (N=64, no relu, fp32 out) ----
    k_gather_h<<<gathBlocks, ZB>>>();
    k_gemm_mma<64, false, false><<<gemmBlocks, 256, SMEM64>>>(
        w + W_L3L, w + W_L3R, b3, out);
}